// round 5
// baseline (speedup 1.0000x reference)
#include <cuda_runtime.h>
#include <cuda_bf16.h>
#include <mma.h>
#include <cstdint>

using namespace nvcuda;

#define NB 64
#define NN 1024
#define ND 128
#define THRESH 0.15f      // 0.5 - MARGIN(0.35)
#define TM 128
#define TN 128
#define LDSE 136          // smem leading dim in bf16 elems (272B rows, 16B aligned)
#define ROWB (LDSE * 2)   // 272 bytes per smem row
#define TILE_BYTES (TM * ROWB)            // 34816
#define BUF_BYTES  (2 * TILE_BYTES)       // A + B = 69632
#define SMEM_TOTAL (2 * BUF_BYTES)        // double buffered = 139264
#define NCTA 148
#define NSLOTS (NB * 8 * 8)               // 4096 (b, ti, tj) slots

// Scratch (device globals; no allocation allowed)
__device__ __nv_bfloat16 g_P[(size_t)NB * NN * ND];
__device__ __nv_bfloat16 g_Q[(size_t)NB * NN * ND];
__device__ unsigned short g_dest[NB * NN];
__device__ int   g_npos[NB];
__device__ int   g_nneg[NB];
__device__ float g_bsum[NB];
__device__ unsigned int g_done;

__device__ __forceinline__ uint32_t smem_u32(const void* p) {
    uint32_t a;
    asm("{ .reg .u64 t; cvta.to.shared.u64 t, %1; cvt.u32.u64 %0, t; }" : "=r"(a) : "l"(p));
    return a;
}
__device__ __forceinline__ void cp16(uint32_t dst, const void* src) {
    asm volatile("cp.async.cg.shared.global [%0], [%1], 16;" :: "r"(dst), "l"(src));
}
#define CP_COMMIT() asm volatile("cp.async.commit_group;" ::: "memory")
#define CP_WAIT(n)  asm volatile("cp.async.wait_group %0;" :: "n"(n) : "memory")

// ---------------------------------------------------------------------------
// Kernel A0: per-batch compaction map via block scan + zero pad rows
// ---------------------------------------------------------------------------
__global__ void __launch_bounds__(1024)
scan_kernel(const int* __restrict__ labels)
{
    const int b = blockIdx.x;
    const int t = threadIdx.x;
    const int lane = t & 31, w = t >> 5;

    __shared__ int wsum[32];

    int p = (labels[b * NN + t] == 1);

    int incl = p;
#pragma unroll
    for (int o = 1; o < 32; o <<= 1) {
        int v = __shfl_up_sync(0xFFFFFFFFu, incl, o);
        if (lane >= o) incl += v;
    }
    if (lane == 31) wsum[w] = incl;
    __syncthreads();
    if (t < 32) {
        int v = wsum[t];
#pragma unroll
        for (int o = 1; o < 32; o <<= 1) {
            int u = __shfl_up_sync(0xFFFFFFFFu, v, o);
            if (lane >= o) v += u;
        }
        wsum[t] = v;
    }
    __syncthreads();

    int ex_pos = incl + (w > 0 ? wsum[w - 1] : 0) - p;
    int ex_neg = t - ex_pos;
    g_dest[b * NN + t] = (unsigned short)((p ? ex_pos : ex_neg) | (p << 15));

    const int npos = wsum[31];
    const int nneg = NN - npos;
    if (t == 0) {
        g_npos[b] = npos; g_nneg[b] = nneg; g_bsum[b] = 0.0f;
        if (b == 0) g_done = 0u;
    }

    // zero-pad tails to 128-row granularity (GEMM then needs no masking)
    const uint4 z4 = make_uint4(0u, 0u, 0u, 0u);
    int pad_pos = min(NN, ((npos + TM - 1) / TM) * TM);
    int pad_neg = min(NN, ((nneg + TN - 1) / TN) * TN);

    int nzp = (pad_pos - npos) * 16;
    for (int i = t; i < nzp; i += 1024) {
        int r = npos + (i >> 4), c = i & 15;
        reinterpret_cast<uint4*>(g_P + ((size_t)b * NN + r) * ND)[c] = z4;
    }
    int nzn = (pad_neg - nneg) * 16;
    for (int i = t; i < nzn; i += 1024) {
        int r = nneg + (i >> 4), c = i & 15;
        reinterpret_cast<uint4*>(g_Q + ((size_t)b * NN + r) * ND)[c] = z4;
    }
}

// ---------------------------------------------------------------------------
// Kernel A1: normalize + compacted scatter. One warp per row.
// ---------------------------------------------------------------------------
__global__ void __launch_bounds__(256)
normalize_scatter_kernel(const float* __restrict__ emb)
{
    const int b = blockIdx.y;
    const int wid  = threadIdx.x >> 5;
    const int lane = threadIdx.x & 31;
    const int r = blockIdx.x * 8 + wid;

    const float* src = emb + ((size_t)b * NN + r) * ND;
    float v[4];
    float ss = 0.0f;
#pragma unroll
    for (int i = 0; i < 4; i++) { v[i] = src[lane + 32 * i]; ss += v[i] * v[i]; }
#pragma unroll
    for (int o = 16; o > 0; o >>= 1) ss += __shfl_xor_sync(0xFFFFFFFFu, ss, o);
    float inv = 1.0f / fmaxf(sqrtf(ss), 1e-12f);

    unsigned short d = g_dest[b * NN + r];
    int rank  = d & 0x7FFF;
    int ispos = d >> 15;
    __nv_bfloat16* dst = (ispos ? g_P : g_Q) + ((size_t)b * NN + rank) * ND;
#pragma unroll
    for (int i = 0; i < 4; i++) dst[lane + 32 * i] = __float2bfloat16(v[i] * inv);
}

// ---------------------------------------------------------------------------
// slot decode + validity
// ---------------------------------------------------------------------------
__device__ __forceinline__ bool slot_valid(int w) {
    int b = w >> 6, ti = (w >> 3) & 7, tj = w & 7;
    return (ti * TM < g_npos[b]) && (tj * TN < g_nneg[b]);
}
__device__ __forceinline__ int next_valid(int w) {
    while (w < NSLOTS && !slot_valid(w)) w += NCTA;
    return w;   // >= NSLOTS means done
}

// ---------------------------------------------------------------------------
// Kernel B: persistent double-buffered wmma GEMM + fused hinge sum + finalize
// grid = 148, block = 256 (8 warps; warp tile 32x64)
// ---------------------------------------------------------------------------
__global__ void __launch_bounds__(256)
hinge_gemm_kernel(float* __restrict__ out)
{
    extern __shared__ __align__(16) char smem[];
    const uint32_t smem_base = smem_u32(smem);
    const int tid  = threadIdx.x;
    const int warp = tid >> 5;
    const int lane = tid & 31;

    __shared__ float s_w[8];

    // issue cp.async fill of (A,B) for slot w into buffer `buf`
    auto prefetch = [&](int w, int buf) {
        int b = w >> 6, ti = (w >> 3) & 7, tj = w & 7;
        const char* P = (const char*)(g_P + ((size_t)b * NN + ti * TM) * ND);
        const char* Q = (const char*)(g_Q + ((size_t)b * NN + tj * TN) * ND);
        uint32_t sA = smem_base + buf * BUF_BYTES;
        uint32_t sB = sA + TILE_BYTES;
        // 128 rows x 16 chunks of 16B per tile; 256 threads -> 8 chunks/thread/tile
        for (int t = tid; t < TM * 16; t += 256) {
            int r = t >> 4, c = t & 15;
            cp16(sA + r * ROWB + c * 16, P + (size_t)r * ND * 2 + c * 16);
            cp16(sB + r * ROWB + c * 16, Q + (size_t)r * ND * 2 + c * 16);
        }
    };

    int cur = next_valid(blockIdx.x);
    int buf = 0;
    if (cur < NSLOTS) { prefetch(cur, 0); CP_COMMIT(); }

    while (cur < NSLOTS) {
        int nxt = next_valid(cur + NCTA);
        if (nxt < NSLOTS) { prefetch(nxt, buf ^ 1); CP_COMMIT(); CP_WAIT(1); }
        else              { CP_WAIT(0); }
        __syncthreads();

        const __nv_bfloat16* sA = (const __nv_bfloat16*)(smem + buf * BUF_BYTES);
        const __nv_bfloat16* sB = (const __nv_bfloat16*)(smem + buf * BUF_BYTES + TILE_BYTES);

        const int wrow = warp >> 1;   // 0..3 -> rows wrow*32
        const int wcol = warp & 1;    // 0..1 -> cols wcol*64

        wmma::fragment<wmma::accumulator, 16, 16, 16, float> acc[2][4];
#pragma unroll
        for (int i = 0; i < 2; i++)
#pragma unroll
            for (int j = 0; j < 4; j++) wmma::fill_fragment(acc[i][j], 0.0f);

#pragma unroll
        for (int k = 0; k < ND; k += 16) {
            wmma::fragment<wmma::matrix_a, 16, 16, 16, __nv_bfloat16, wmma::row_major> a[2];
            wmma::fragment<wmma::matrix_b, 16, 16, 16, __nv_bfloat16, wmma::col_major> bb[4];
#pragma unroll
            for (int i = 0; i < 2; i++)
                wmma::load_matrix_sync(a[i], sA + (wrow * 32 + i * 16) * LDSE + k, LDSE);
#pragma unroll
            for (int j = 0; j < 4; j++)
                wmma::load_matrix_sync(bb[j], sB + (wcol * 64 + j * 16) * LDSE + k, LDSE);
#pragma unroll
            for (int i = 0; i < 2; i++)
#pragma unroll
                for (int j = 0; j < 4; j++)
                    wmma::mma_sync(acc[i][j], a[i], bb[j], acc[i][j]);
        }

        float s = 0.0f;
#pragma unroll
        for (int i = 0; i < 2; i++)
#pragma unroll
            for (int j = 0; j < 4; j++)
#pragma unroll
                for (int e = 0; e < acc[i][j].num_elements; e++)
                    s += fmaxf(acc[i][j].x[e] - THRESH, 0.0f);
#pragma unroll
        for (int o = 16; o > 0; o >>= 1) s += __shfl_xor_sync(0xFFFFFFFFu, s, o);
        if (lane == 0) s_w[warp] = s;
        __syncthreads();
        if (tid == 0) {
            float ts = 0.0f;
#pragma unroll
            for (int i = 0; i < 8; i++) ts += s_w[i];
            atomicAdd(&g_bsum[cur >> 6], ts);
        }
        __syncthreads();   // buffer `buf` free for reuse; s_w consumed

        cur = nxt;
        buf ^= 1;
    }

    // completion ticket; last CTA computes the final scalar
    __shared__ unsigned int s_rank;
    if (tid == 0) {
        __threadfence();
        s_rank = atomicAdd(&g_done, 1u);
    }
    __syncthreads();
    if (s_rank == NCTA - 1 && tid == 0) {
        __threadfence();
        float L = 0.0f, C = 0.0f;
        for (int i = 0; i < NB; i++) {
            int np = g_npos[i], nn = g_nneg[i];
            if (np > 0 && nn > 0) {
                L += g_bsum[i] / (float)nn;
                C += (float)np;
            }
        }
        out[0] = L / fmaxf(C, 1.0f);
    }
}

// ---------------------------------------------------------------------------
extern "C" void kernel_launch(void* const* d_in, const int* in_sizes, int n_in,
                              void* d_out, int out_size)
{
    const float* emb    = (const float*)d_in[0];
    const int*   labels = (const int*)d_in[1];
    float*       out    = (float*)d_out;

    cudaFuncSetAttribute(hinge_gemm_kernel,
                         cudaFuncAttributeMaxDynamicSharedMemorySize, SMEM_TOTAL);

    scan_kernel<<<NB, 1024>>>(labels);

    dim3 gridA(NN / 8, NB);
    normalize_scatter_kernel<<<gridA, 256>>>(emb);

    hinge_gemm_kernel<<<NCTA, 256, SMEM_TOTAL>>>(out);
}